// round 8
// baseline (speedup 1.0000x reference)
#include <cuda_runtime.h>
#include <cuda_fp16.h>
#include <mma.h>
#include <cstdint>

using namespace nvcuda;

#define TSTEPS 512
#define BATCH  128
#define HID    1024
#define NG     4096
#define NLAYER 2
#define NCTA_R 128
#define THR_R  256   // 8 warps

// ---------------- device scratch ----------------
__device__ float  g_gatesT[(size_t)TSTEPS * NG * BATCH];          // [t][col][b]
__device__ __align__(16) __half g_hseq16[(size_t)TSTEPS * BATCH * HID];
__device__ __align__(16) __half g_h16[2][BATCH * HID];            // ping-pong h
__device__ __align__(16) float  g_part[NCTA_R][BATCH * 32];       // pair-exchange partials
__device__ int  g_flag[NCTA_R * 32];                              // pair flags (stride 32 ints)
__device__ unsigned int g_count;

// ---------------- recurrence smem layout (bytes) ----------------
// W: 512 x 72 half = 73728 ; A: 3 x (128 x 136 half) = 104448 ; G: 128 x 68 float = 34816
#define SM_W     0
#define SM_A     73728
#define SM_ABUF  34816
#define SM_G     178176
#define SM_BIAS  212992      // 64 floats
#define SM_TOTAL 213248

__device__ __forceinline__ uint32_t smem_u32(const void* p) {
    uint32_t a;
    asm("{ .reg .u64 t; cvta.to.shared.u64 t, %1; cvt.u32.u64 %0, t; }" : "=r"(a) : "l"(p));
    return a;
}
__device__ __forceinline__ void cp16(uint32_t dst, const void* src) {
    asm volatile("cp.async.cg.shared.global [%0], [%1], 16;" :: "r"(dst), "l"(src));
}
#define CP_COMMIT() asm volatile("cp.async.commit_group;" ::: "memory")
#define CP_WAIT1()  asm volatile("cp.async.wait_group 1;" ::: "memory")
#define CP_WAIT0()  asm volatile("cp.async.wait_group 0;" ::: "memory")

__device__ __forceinline__ float sigf(float x) { return 1.f / (1.f + __expf(-x)); }
__device__ __forceinline__ uint32_t packh2(float a, float b) {
    return (uint32_t)__half_as_ushort(__float2half_rn(a)) |
           ((uint32_t)__half_as_ushort(__float2half_rn(b)) << 16);
}

// =================================================================================
// Input GEMM (unchanged)
// =================================================================================
template<bool AHALF>
__global__ void __launch_bounds__(256) gemm_input(const void* __restrict__ Av,
                                                  const float* __restrict__ W,
                                                  float* __restrict__ CT)
{
    __shared__ __half As[128][40];
    __shared__ __half Bs[32][136];

    const int tid  = threadIdx.x;
    const int warp = tid >> 5;
    const int wm = warp >> 2;
    const int wn = warp & 3;
    const int bm = blockIdx.y;
    const int bn = blockIdx.x;

    const int arow = tid >> 1, acol = (tid & 1) * 16;
    const int brow = tid >> 3, bcol = (tid & 7) * 16;

    const float*  Af = (const float*) Av;
    const __half* Ah = (const __half*)Av;
    const size_t  a_off = (size_t)(bm * 128 + arow) * 1024 + acol;
    const float*  Wg = W + (size_t)brow * NG + bn * 128 + bcol;

    wmma::fragment<wmma::accumulator, 16, 16, 16, float> acc[4][2];
#pragma unroll
    for (int i = 0; i < 4; i++)
#pragma unroll
        for (int j = 0; j < 2; j++) wmma::fill_fragment(acc[i][j], 0.f);

    float4 ra[4]; uint4 ra16[2]; float4 rb[4];
    if (AHALF) {
        ra16[0] = ((const uint4*)(Ah + a_off))[0];
        ra16[1] = ((const uint4*)(Ah + a_off))[1];
    } else {
#pragma unroll
        for (int i = 0; i < 4; i++) ra[i] = *(const float4*)(Af + a_off + i * 4);
    }
#pragma unroll
    for (int i = 0; i < 4; i++) rb[i] = *(const float4*)(Wg + i * 4);

    for (int k0 = 0; k0 < 1024; k0 += 32) {
        __syncthreads();
        if (AHALF) {
            *(uint4*)&As[arow][acol]     = ra16[0];
            *(uint4*)&As[arow][acol + 8] = ra16[1];
        } else {
            *(uint4*)&As[arow][acol] = make_uint4(
                packh2(ra[0].x, ra[0].y), packh2(ra[0].z, ra[0].w),
                packh2(ra[1].x, ra[1].y), packh2(ra[1].z, ra[1].w));
            *(uint4*)&As[arow][acol + 8] = make_uint4(
                packh2(ra[2].x, ra[2].y), packh2(ra[2].z, ra[2].w),
                packh2(ra[3].x, ra[3].y), packh2(ra[3].z, ra[3].w));
        }
        *(uint4*)&Bs[brow][bcol] = make_uint4(
            packh2(rb[0].x, rb[0].y), packh2(rb[0].z, rb[0].w),
            packh2(rb[1].x, rb[1].y), packh2(rb[1].z, rb[1].w));
        *(uint4*)&Bs[brow][bcol + 8] = make_uint4(
            packh2(rb[2].x, rb[2].y), packh2(rb[2].z, rb[2].w),
            packh2(rb[3].x, rb[3].y), packh2(rb[3].z, rb[3].w));
        __syncthreads();

        const int kn = k0 + 32;
        if (kn < 1024) {
            if (AHALF) {
                ra16[0] = ((const uint4*)(Ah + a_off + kn))[0];
                ra16[1] = ((const uint4*)(Ah + a_off + kn))[1];
            } else {
#pragma unroll
                for (int i = 0; i < 4; i++) ra[i] = *(const float4*)(Af + a_off + kn + i * 4);
            }
#pragma unroll
            for (int i = 0; i < 4; i++) rb[i] = *(const float4*)(Wg + (size_t)kn * NG + i * 4);
        }

#pragma unroll
        for (int kk = 0; kk < 32; kk += 16) {
            wmma::fragment<wmma::matrix_a, 16, 16, 16, __half, wmma::row_major> fa[4];
            wmma::fragment<wmma::matrix_b, 16, 16, 16, __half, wmma::row_major> fb[2];
#pragma unroll
            for (int i = 0; i < 4; i++)
                wmma::load_matrix_sync(fa[i], &As[wm * 64 + i * 16][kk], 40);
#pragma unroll
            for (int j = 0; j < 2; j++)
                wmma::load_matrix_sync(fb[j], &Bs[kk][wn * 32 + j * 16], 136);
#pragma unroll
            for (int i = 0; i < 4; i++)
#pragma unroll
                for (int j = 0; j < 2; j++)
                    wmma::mma_sync(acc[i][j], fa[i], fb[j], acc[i][j]);
        }
    }

    float* base = CT + (size_t)bm * NG * 128;
#pragma unroll
    for (int i = 0; i < 4; i++)
#pragma unroll
        for (int j = 0; j < 2; j++) {
            const int col = bn * 128 + wn * 32 + j * 16;
            const int b   = wm * 64 + i * 16;
            wmma::store_matrix_sync(base + (size_t)col * 128 + b, acc[i][j],
                                    128, wmma::mem_col_major);
        }
}

// =================================================================================
__global__ void lstm_init()
{
    const int i = blockIdx.x * blockDim.x + threadIdx.x;   // 65536
    if (i == 0) g_count = 0;
    if (i < NCTA_R * 32) g_flag[i] = 0;
    ((uint32_t*)g_h16[0])[i] = 0u;
}

// =================================================================================
// Persistent recurrence, PAIR-SPLIT K. 128 CTAs x 256 threads.
// Pair p = bx>>1 owns j-cols [16p,16p+16) (64 gate-cols, n = jl*4+gate).
// Member e = bx&1 contracts k in [e*512,(e+1)*512) -> reads only HALF of h/step.
// Partial gates for the partner's 8 j-cols are sent via global scratch + flag.
// Warp tile M32 x N32 over K512; 4 chunks of K=128, 3 smem buffers, 1 sync/chunk.
// =================================================================================
__global__ void __launch_bounds__(THR_R, 1) lstm_recur(
    const float* __restrict__ Whh,      // [HID, NG]
    const float* __restrict__ gatesT,   // [T][col][b]
    const float* __restrict__ b1, const float* __restrict__ b2,
    __half* __restrict__ seq16,         // layer-0 output (or null)
    float*  __restrict__ seq32,         // last-layer output (or null)
    float* __restrict__ hT, float* __restrict__ cT)
{
    extern __shared__ __align__(16) char smem[];
    __half* Ws   = (__half*)(smem + SM_W);          // [512][72]
    float*  Gs   = (float*) (smem + SM_G);          // [128][68]
    float*  bias = (float*) (smem + SM_BIAS);       // [64]
    const uint32_t sbase = smem_u32(smem);

    const int tid   = threadIdx.x;
    const int wid   = tid >> 5;
    const int mquad = wid & 3;          // M strip: rows mquad*32..+32
    const int npos  = wid >> 2;         // N half: cols npos*32..+32
    const int bx  = blockIdx.x;
    const int p   = bx >> 1;            // pair id
    const int e   = bx & 1;             // member
    const int px  = bx ^ 1;             // partner CTA
    const int jp0 = p * 16;             // pair j base
    const int kofs = e * 512;           // my K offset into h

    // ---- stage W slice (fp16) + bias, once ----
    for (int idx = tid; idx < 512 * 64; idx += THR_R) {
        const int k = idx >> 6, n = idx & 63;
        const int gate = n & 3, jl = n >> 2;
        Ws[k * 72 + n] = __float2half_rn(
            Whh[(size_t)(kofs + k) * NG + gate * HID + jp0 + jl]);
    }
    if (tid < 64) {
        const int gate = tid & 3, jl = tid >> 2;
        bias[tid] = b1[gate * HID + jp0 + jl] + b2[gate * HID + jp0 + jl];
    }
    __syncthreads();

    // cell mapping: thread -> batch row m, 4 j-cols (own j = e*8 + jhalf*4 + q)
    const int m     = tid & 127;
    const int jhalf = tid >> 7;
    const int jglob0 = jp0 + e * 8 + jhalf * 4;
    float c4[4];
#pragma unroll
    for (int q = 0; q < 4; q++) c4[q] = 0.f;

    float* mypart  = g_part[bx];        // partner writes here for me
    float* hispart = g_part[px];        // I write partner's half here
    volatile int* myflag  = g_flag + bx * 32;
    volatile int* hisflag = g_flag + px * 32;

    for (int t = 0; t < TSTEPS; ++t) {
        const __half* hin  = g_h16[t & 1];
        __half*       hout = g_h16[(t + 1) & 1];

        // ---- prefetch input-projection slice for own cols ----
        float gt[16];
        {
            const float* gb = gatesT + (size_t)t * NG * BATCH + m;
#pragma unroll
            for (int q = 0; q < 4; q++)
#pragma unroll
                for (int g = 0; g < 4; g++)
                    gt[q * 4 + g] = gb[(size_t)(g * HID + jglob0 + q) * BATCH];
        }

        wmma::fragment<wmma::accumulator, 16, 16, 16, float> acc[2][2];
#pragma unroll
        for (int i = 0; i < 2; i++)
#pragma unroll
            for (int j = 0; j < 2; j++) wmma::fill_fragment(acc[i][j], 0.f);

        // ---- stage chunks 0,1 up front (depth-2 prefetch) ----
#pragma unroll
        for (int c = 0; c < 2; ++c) {
            const uint32_t dbase = sbase + SM_A + c * SM_ABUF;
            const __half* hp = hin + kofs + c * 128;
#pragma unroll
            for (int u = 0; u < 8; u++) {
                const int idx = u * THR_R + tid;
                const int row = idx >> 4, kc = (idx & 15) * 8;
                cp16(dbase + (uint32_t)(row * 272 + kc * 2),
                     hp + (size_t)row * HID + kc);
            }
            CP_COMMIT();
        }

        // ---- 4 chunks, 3 buffers, 1 sync per chunk ----
#pragma unroll 1
        for (int cc = 0; cc < 4; ++cc) {
            if (cc < 3) CP_WAIT1(); else CP_WAIT0();
            __syncthreads();

            if (cc < 2) {   // stage chunk cc+2 into buf (cc+2)%3
                const int cn = cc + 2;
                const uint32_t dbase = sbase + SM_A + (cn % 3) * SM_ABUF;
                const __half* hp = hin + kofs + cn * 128;
#pragma unroll
                for (int u = 0; u < 8; u++) {
                    const int idx = u * THR_R + tid;
                    const int row = idx >> 4, kc = (idx & 15) * 8;
                    cp16(dbase + (uint32_t)(row * 272 + kc * 2),
                         hp + (size_t)row * HID + kc);
                }
                CP_COMMIT();
            }

            const __half* Ap = (const __half*)(smem + SM_A + (cc % 3) * SM_ABUF)
                             + (size_t)mquad * 32 * 136;
            const __half* Wp = Ws + (size_t)cc * 128 * 72 + npos * 32;
#pragma unroll
            for (int kk = 0; kk < 128; kk += 16) {
                wmma::fragment<wmma::matrix_a, 16, 16, 16, __half, wmma::row_major> fa[2];
                wmma::fragment<wmma::matrix_b, 16, 16, 16, __half, wmma::row_major> fb[2];
#pragma unroll
                for (int i = 0; i < 2; i++)
                    wmma::load_matrix_sync(fa[i], Ap + (size_t)(i * 16) * 136 + kk, 136);
#pragma unroll
                for (int j = 0; j < 2; j++)
                    wmma::load_matrix_sync(fb[j], Wp + (size_t)kk * 72 + j * 16, 72);
#pragma unroll
                for (int i = 0; i < 2; i++)
#pragma unroll
                    for (int j = 0; j < 2; j++)
                        wmma::mma_sync(acc[i][j], fa[i], fb[j], acc[i][j]);
            }
        }

        // ---- gate tile to smem ----
        __syncthreads();   // A buffers done; Gs region is separate but acc stores need all reads done anyway
#pragma unroll
        for (int i = 0; i < 2; i++)
#pragma unroll
            for (int j = 0; j < 2; j++)
                wmma::store_matrix_sync(Gs + (size_t)(mquad * 32 + i * 16) * 68 + npos * 32 + j * 16,
                                        acc[i][j], 68, wmma::mem_row_major);
        __syncthreads();

        // ---- send partner's 32 gate-cols (n in [(1-e)*32, +32)) ----
        {
            const int nb = (1 - e) * 32;
#pragma unroll
            for (int u = 0; u < 4; u++) {
                const int idx4 = u * THR_R + tid;       // 1024 float4s
                const int mr = idx4 >> 3, c4i = (idx4 & 7) * 4;
                *(float4*)(hispart + mr * 32 + c4i) =
                    *(const float4*)(Gs + (size_t)mr * 68 + nb + c4i);
            }
        }
        __threadfence();
        __syncthreads();
        if (tid == 0) {
            *myflag = t + 1;
            while (*hisflag < t + 1) { }
        }
        __syncthreads();
        __threadfence();   // acquire: order partner-partial reads after flag

        // ---- LSTM cell: own 32 gate-cols, 4 j per thread ----
        float hn[4];
#pragma unroll
        for (int q = 0; q < 4; q++) {
            const int nl = e * 32 + jhalf * 16 + q * 4;     // own col block
            const float4 vo = *(const float4*)(Gs + (size_t)m * 68 + nl);
            const float4 vp = __ldcg((const float4*)(mypart + m * 32 + jhalf * 16 + q * 4));
            const float zi = vo.x + vp.x + gt[q * 4 + 0] + bias[nl + 0];
            const float zf = vo.y + vp.y + gt[q * 4 + 1] + bias[nl + 1];
            const float zg = vo.z + vp.z + gt[q * 4 + 2] + bias[nl + 2];
            const float zo = vo.w + vp.w + gt[q * 4 + 3] + bias[nl + 3];
            const float cn = sigf(zf) * c4[q] + sigf(zi) * tanhf(zg);
            hn[q] = sigf(zo) * tanhf(cn);
            c4[q] = cn;
        }

        const size_t ob = (size_t)m * HID + jglob0;
        {
            uint2 u = make_uint2(packh2(hn[0], hn[1]), packh2(hn[2], hn[3]));
            *(uint2*)(hout + ob) = u;
            if (seq16) *(uint2*)(seq16 + (size_t)t * BATCH * HID + ob) = u;
        }
        if (seq32)
            *(float4*)(seq32 + (size_t)t * BATCH * HID + ob) =
                make_float4(hn[0], hn[1], hn[2], hn[3]);
        if (t == TSTEPS - 1) {
            *(float4*)(hT + ob) = make_float4(hn[0], hn[1], hn[2], hn[3]);
            *(float4*)(cT + ob) = make_float4(c4[0], c4[1], c4[2], c4[3]);
        }

        // ---- global generation barrier ----
        __threadfence();
        __syncthreads();
        if (tid == 0) {
            atomicAdd(&g_count, 1u);
            const unsigned target = (unsigned)(t + 1) * gridDim.x;
            while (*(volatile unsigned*)&g_count < target) { }
        }
        __syncthreads();
    }
}

// =================================================================================
extern "C" void kernel_launch(void* const* d_in, const int* in_sizes, int n_in,
                              void* d_out, int out_size)
{
    const float* x   = (const float*)d_in[0];
    const float* wih = (const float*)d_in[1];
    const float* whh = (const float*)d_in[2];
    const float* bih = (const float*)d_in[3];
    const float* bhh = (const float*)d_in[4];
    float* out = (float*)d_out;

    cudaFuncSetAttribute(lstm_recur, cudaFuncAttributeMaxDynamicSharedMemorySize, SM_TOTAL);

    float  *gatesT;
    __half *hseq16;
    cudaGetSymbolAddress((void**)&gatesT, g_gatesT);
    cudaGetSymbolAddress((void**)&hseq16, g_hseq16);

    float* hT_base = out + (size_t)TSTEPS * BATCH * HID;
    float* cT_base = hT_base + (size_t)NLAYER * BATCH * HID;

    for (int l = 0; l < NLAYER; ++l) {
        const float* Wih = wih + (size_t)l * 1024 * NG;
        const float* Whh = whh + (size_t)l * HID * NG;
        const float* B1  = bih + (size_t)l * NG;
        const float* B2  = bhh + (size_t)l * NG;
        float* hT = hT_base + (size_t)l * BATCH * HID;
        float* cT = cT_base + (size_t)l * BATCH * HID;

        if (l == 0)
            gemm_input<false><<<dim3(NG / 128, TSTEPS), 256>>>(x, Wih, gatesT);
        else
            gemm_input<true ><<<dim3(NG / 128, TSTEPS), 256>>>(hseq16, Wih, gatesT);

        lstm_init<<<256, 256>>>();

        lstm_recur<<<NCTA_R, THR_R, SM_TOTAL>>>(
            Whh, gatesT, B1, B2,
            (l == 0) ? hseq16 : (__half*)nullptr,
            (l == 1) ? out    : (float*)nullptr,
            hT, cT);
    }
}

// round 9
// speedup vs baseline: 1.0705x; 1.0705x over previous
#include <cuda_runtime.h>
#include <cuda_fp16.h>
#include <mma.h>
#include <cstdint>

using namespace nvcuda;

#define TSTEPS 512
#define BATCH  128
#define HID    1024
#define NG     4096
#define NLAYER 2
#define NCTA_R 128
#define THR_R  256   // 8 warps: 4 mquad x 2 khalf

// ---------------- device scratch ----------------
__device__ float  g_gatesT[(size_t)TSTEPS * NG * BATCH];          // [t][col][b]
__device__ __align__(16) __half g_hseq16[(size_t)TSTEPS * BATCH * HID];
__device__ __align__(16) __half g_h16[2][BATCH * HID];            // ping-pong h
__device__ unsigned int g_count;

// ---------------- recurrence smem layout (bytes) ----------------
// W: 1024 x 40 half = 81920 ; A: 3 x (128 x 136 half) = 104448 ;
// G: 2 x (128 x 40 float) = 40960 ; bias 256
#define SM_W     0
#define SM_A     81920
#define SM_ABUF  34816
#define SM_G     186368
#define SM_BIAS  227328
#define SM_TOTAL 227584

__device__ __forceinline__ uint32_t smem_u32(const void* p) {
    uint32_t a;
    asm("{ .reg .u64 t; cvta.to.shared.u64 t, %1; cvt.u32.u64 %0, t; }" : "=r"(a) : "l"(p));
    return a;
}
__device__ __forceinline__ void cp16(uint32_t dst, const void* src) {
    asm volatile("cp.async.cg.shared.global [%0], [%1], 16;" :: "r"(dst), "l"(src));
}
#define CP_COMMIT() asm volatile("cp.async.commit_group;" ::: "memory")
#define CP_WAIT1()  asm volatile("cp.async.wait_group 1;" ::: "memory")
#define CP_WAIT0()  asm volatile("cp.async.wait_group 0;" ::: "memory")

__device__ __forceinline__ void rel_add1(unsigned int* p) {
    asm volatile("red.release.gpu.global.add.u32 [%0], 1;" :: "l"(p) : "memory");
}
__device__ __forceinline__ unsigned int acq_ld(const unsigned int* p) {
    unsigned int v;
    asm volatile("ld.acquire.gpu.global.u32 %0, [%1];" : "=r"(v) : "l"(p) : "memory");
    return v;
}

__device__ __forceinline__ float sigf(float x) { return 1.f / (1.f + __expf(-x)); }
__device__ __forceinline__ uint32_t packh2(float a, float b) {
    return (uint32_t)__half_as_ushort(__float2half_rn(a)) |
           ((uint32_t)__half_as_ushort(__float2half_rn(b)) << 16);
}

// =================================================================================
// Input GEMM (unchanged — controlled experiment on the recurrence)
// =================================================================================
template<bool AHALF>
__global__ void __launch_bounds__(256) gemm_input(const void* __restrict__ Av,
                                                  const float* __restrict__ W,
                                                  float* __restrict__ CT)
{
    __shared__ __half As[128][40];
    __shared__ __half Bs[32][136];

    const int tid  = threadIdx.x;
    const int warp = tid >> 5;
    const int wm = warp >> 2;
    const int wn = warp & 3;
    const int bm = blockIdx.y;
    const int bn = blockIdx.x;

    const int arow = tid >> 1, acol = (tid & 1) * 16;
    const int brow = tid >> 3, bcol = (tid & 7) * 16;

    const float*  Af = (const float*) Av;
    const __half* Ah = (const __half*)Av;
    const size_t  a_off = (size_t)(bm * 128 + arow) * 1024 + acol;
    const float*  Wg = W + (size_t)brow * NG + bn * 128 + bcol;

    wmma::fragment<wmma::accumulator, 16, 16, 16, float> acc[4][2];
#pragma unroll
    for (int i = 0; i < 4; i++)
#pragma unroll
        for (int j = 0; j < 2; j++) wmma::fill_fragment(acc[i][j], 0.f);

    float4 ra[4]; uint4 ra16[2]; float4 rb[4];
    if (AHALF) {
        ra16[0] = ((const uint4*)(Ah + a_off))[0];
        ra16[1] = ((const uint4*)(Ah + a_off))[1];
    } else {
#pragma unroll
        for (int i = 0; i < 4; i++) ra[i] = *(const float4*)(Af + a_off + i * 4);
    }
#pragma unroll
    for (int i = 0; i < 4; i++) rb[i] = *(const float4*)(Wg + i * 4);

    for (int k0 = 0; k0 < 1024; k0 += 32) {
        __syncthreads();
        if (AHALF) {
            *(uint4*)&As[arow][acol]     = ra16[0];
            *(uint4*)&As[arow][acol + 8] = ra16[1];
        } else {
            *(uint4*)&As[arow][acol] = make_uint4(
                packh2(ra[0].x, ra[0].y), packh2(ra[0].z, ra[0].w),
                packh2(ra[1].x, ra[1].y), packh2(ra[1].z, ra[1].w));
            *(uint4*)&As[arow][acol + 8] = make_uint4(
                packh2(ra[2].x, ra[2].y), packh2(ra[2].z, ra[2].w),
                packh2(ra[3].x, ra[3].y), packh2(ra[3].z, ra[3].w));
        }
        *(uint4*)&Bs[brow][bcol] = make_uint4(
            packh2(rb[0].x, rb[0].y), packh2(rb[0].z, rb[0].w),
            packh2(rb[1].x, rb[1].y), packh2(rb[1].z, rb[1].w));
        *(uint4*)&Bs[brow][bcol + 8] = make_uint4(
            packh2(rb[2].x, rb[2].y), packh2(rb[2].z, rb[2].w),
            packh2(rb[3].x, rb[3].y), packh2(rb[3].z, rb[3].w));
        __syncthreads();

        const int kn = k0 + 32;
        if (kn < 1024) {
            if (AHALF) {
                ra16[0] = ((const uint4*)(Ah + a_off + kn))[0];
                ra16[1] = ((const uint4*)(Ah + a_off + kn))[1];
            } else {
#pragma unroll
                for (int i = 0; i < 4; i++) ra[i] = *(const float4*)(Af + a_off + kn + i * 4);
            }
#pragma unroll
            for (int i = 0; i < 4; i++) rb[i] = *(const float4*)(Wg + (size_t)kn * NG + i * 4);
        }

#pragma unroll
        for (int kk = 0; kk < 32; kk += 16) {
            wmma::fragment<wmma::matrix_a, 16, 16, 16, __half, wmma::row_major> fa[4];
            wmma::fragment<wmma::matrix_b, 16, 16, 16, __half, wmma::row_major> fb[2];
#pragma unroll
            for (int i = 0; i < 4; i++)
                wmma::load_matrix_sync(fa[i], &As[wm * 64 + i * 16][kk], 40);
#pragma unroll
            for (int j = 0; j < 2; j++)
                wmma::load_matrix_sync(fb[j], &Bs[kk][wn * 32 + j * 16], 136);
#pragma unroll
            for (int i = 0; i < 4; i++)
#pragma unroll
                for (int j = 0; j < 2; j++)
                    wmma::mma_sync(acc[i][j], fa[i], fb[j], acc[i][j]);
        }
    }

    float* base = CT + (size_t)bm * NG * 128;
#pragma unroll
    for (int i = 0; i < 4; i++)
#pragma unroll
        for (int j = 0; j < 2; j++) {
            const int col = bn * 128 + wn * 32 + j * 16;
            const int b   = wm * 64 + i * 16;
            wmma::store_matrix_sync(base + (size_t)col * 128 + b, acc[i][j],
                                    128, wmma::mem_col_major);
        }
}

// =================================================================================
__global__ void lstm_init()
{
    const int i = blockIdx.x * blockDim.x + threadIdx.x;   // 65536
    if (i == 0) g_count = 0;
    ((uint32_t*)g_h16[0])[i] = 0u;
}

// =================================================================================
// Persistent fp16 HMMA recurrence. 128 CTAs x 256 threads (4 mquad x 2 khalf).
// CTA bx owns hidden cols [bx*8, bx*8+8) (N=32 gate-cols, n = jl*4 + gate).
// Step skeleton minimized: 8 chunks x 1 sync (3-buffer cp.async), split-phase
// global barrier (release-arrive, work shadow = seq stores + next gt prefetch,
// acquire-wait), no full threadfences.
// =================================================================================
__global__ void __launch_bounds__(THR_R, 1) lstm_recur(
    const float* __restrict__ Whh,      // [HID, NG]
    const float* __restrict__ gatesT,   // [T][col][b]
    const float* __restrict__ b1, const float* __restrict__ b2,
    __half* __restrict__ seq16,         // layer-0 output (or null)
    float*  __restrict__ seq32,         // last-layer output (or null)
    float* __restrict__ hT, float* __restrict__ cT)
{
    extern __shared__ __align__(16) char smem[];
    __half* Ws   = (__half*)(smem + SM_W);       // [1024][40]
    float*  Gs0  = (float*) (smem + SM_G);       // [128][40]
    float*  Gs1  = Gs0 + 128 * 40;
    float*  bias = (float*) (smem + SM_BIAS);    // [32]
    const uint32_t sbase = smem_u32(smem);

    const int tid   = threadIdx.x;
    const int wid   = tid >> 5;
    const int mquad = wid & 3;          // rows mquad*32..+32
    const int khalf = wid >> 2;         // 0: kk<64 of chunk, 1: kk>=64
    const int bx  = blockIdx.x;
    const int j0  = bx * 8;

    // ---- stage W slice (fp16) + bias, once ----
    for (int idx = tid; idx < 1024 * 32; idx += THR_R) {
        const int k = idx >> 5, n = idx & 31;
        const int gate = n & 3, jl = n >> 2;
        Ws[k * 40 + n] = __float2half_rn(Whh[(size_t)k * NG + gate * HID + j0 + jl]);
    }
    if (tid < 32) {
        const int gate = tid & 3, jl = tid >> 2;
        bias[tid] = b1[gate * HID + j0 + jl] + b2[gate * HID + j0 + jl];
    }
    __syncthreads();

    // cell mapping: thread -> batch row m, 4 hidden cols (jl = nhalf*4 + q)
    const int m     = tid & 127;
    const int nhalf = tid >> 7;
    float c4[4];
#pragma unroll
    for (int q = 0; q < 4; q++) c4[q] = 0.f;

    // gt prefetch for t = 0
    float gt[16];
    {
        const float* gb = gatesT + m;
#pragma unroll
        for (int q = 0; q < 4; q++)
#pragma unroll
            for (int g = 0; g < 4; g++)
                gt[q * 4 + g] = gb[(size_t)(g * HID + j0 + nhalf * 4 + q) * BATCH];
    }

    for (int t = 0; t < TSTEPS; ++t) {
        // ---- wait for generation t (hin ready); t=0 ready via launch order ----
        if (t > 0) {
            if (tid == 0) {
                const unsigned target = (unsigned)t * NCTA_R;
                while (acq_ld(&g_count) < target) { }
            }
            __syncthreads();
        }

        const __half* hin  = g_h16[t & 1];
        __half*       hout = g_h16[(t + 1) & 1];

        wmma::fragment<wmma::accumulator, 16, 16, 16, float> acc[2][2];
#pragma unroll
        for (int i = 0; i < 2; i++)
#pragma unroll
            for (int j = 0; j < 2; j++) wmma::fill_fragment(acc[i][j], 0.f);

        // ---- stage chunks 0,1 (depth-2) ----
#pragma unroll
        for (int c = 0; c < 2; ++c) {
            const uint32_t dbase = sbase + SM_A + c * SM_ABUF;
            const __half* hp = hin + c * 128;
#pragma unroll
            for (int u = 0; u < 8; u++) {
                const int idx = u * THR_R + tid;
                const int row = idx >> 4, k8 = (idx & 15) * 8;
                cp16(dbase + (uint32_t)(row * 136 + k8) * 2,
                     hp + (size_t)row * HID + k8);
            }
            CP_COMMIT();
        }

        // ---- 8 chunks, 3 buffers, 1 sync per chunk ----
#pragma unroll 1
        for (int cc = 0; cc < 8; ++cc) {
            if (cc < 7) CP_WAIT1(); else CP_WAIT0();
            __syncthreads();

            if (cc < 6) {   // stage chunk cc+2 into buf (cc+2)%3
                const int cn = cc + 2;
                const uint32_t dbase = sbase + SM_A + (cn % 3) * SM_ABUF;
                const __half* hp = hin + cn * 128;
#pragma unroll
                for (int u = 0; u < 8; u++) {
                    const int idx = u * THR_R + tid;
                    const int row = idx >> 4, k8 = (idx & 15) * 8;
                    cp16(dbase + (uint32_t)(row * 136 + k8) * 2,
                         hp + (size_t)row * HID + k8);
                }
                CP_COMMIT();
            }

            const __half* Ap = (const __half*)(smem + SM_A + (cc % 3) * SM_ABUF)
                             + (size_t)mquad * 32 * 136 + khalf * 64;
            const __half* Wp = Ws + (size_t)(cc * 128 + khalf * 64) * 40;
#pragma unroll
            for (int kk = 0; kk < 64; kk += 16) {
                wmma::fragment<wmma::matrix_a, 16, 16, 16, __half, wmma::row_major> fa[2];
                wmma::fragment<wmma::matrix_b, 16, 16, 16, __half, wmma::row_major> fb[2];
#pragma unroll
                for (int i = 0; i < 2; i++)
                    wmma::load_matrix_sync(fa[i], Ap + (size_t)(i * 16) * 136 + kk, 136);
#pragma unroll
                for (int j = 0; j < 2; j++)
                    wmma::load_matrix_sync(fb[j], Wp + (size_t)kk * 40 + j * 16, 40);
#pragma unroll
                for (int i = 0; i < 2; i++)
#pragma unroll
                    for (int j = 0; j < 2; j++)
                        wmma::mma_sync(acc[i][j], fa[i], fb[j], acc[i][j]);
            }
        }

        // ---- partial gate tiles (Gs region disjoint from A buffers) ----
        float* Gsw = khalf ? Gs1 : Gs0;
#pragma unroll
        for (int i = 0; i < 2; i++)
#pragma unroll
            for (int j = 0; j < 2; j++)
                wmma::store_matrix_sync(Gsw + (size_t)(mquad * 32 + i * 16) * 40 + j * 16,
                                        acc[i][j], 40, wmma::mem_row_major);
        __syncthreads();

        // ---- LSTM cell ----
        float hn[4];
#pragma unroll
        for (int q = 0; q < 4; q++) {
            const int n = nhalf * 16 + q * 4;
            const float4 v0 = *(const float4*)(Gs0 + (size_t)m * 40 + n);
            const float4 v1 = *(const float4*)(Gs1 + (size_t)m * 40 + n);
            const float zi = v0.x + v1.x + gt[q * 4 + 0] + bias[n + 0];
            const float zf = v0.y + v1.y + gt[q * 4 + 1] + bias[n + 1];
            const float zg = v0.z + v1.z + gt[q * 4 + 2] + bias[n + 2];
            const float zo = v0.w + v1.w + gt[q * 4 + 3] + bias[n + 3];
            const float cn = sigf(zf) * c4[q] + sigf(zi) * tanhf(zg);
            hn[q] = sigf(zo) * tanhf(cn);
            c4[q] = cn;
        }

        // ---- publish h, arrive ----
        const size_t ob = (size_t)m * HID + j0 + nhalf * 4;
        const uint2 upk = make_uint2(packh2(hn[0], hn[1]), packh2(hn[2], hn[3]));
        *(uint2*)(hout + ob) = upk;

        __syncthreads();                   // all hout stores done CTA-wide
        if (tid == 0) rel_add1(&g_count);  // release-arrive (publishes CTA's writes)

        // ---- work shadow (overlaps other CTAs + own wait) ----
        if (seq16) *(uint2*)(seq16 + (size_t)t * BATCH * HID + ob) = upk;
        if (seq32)
            *(float4*)(seq32 + (size_t)t * BATCH * HID + ob) =
                make_float4(hn[0], hn[1], hn[2], hn[3]);
        if (t == TSTEPS - 1) {
            *(float4*)(hT + ob) = make_float4(hn[0], hn[1], hn[2], hn[3]);
            *(float4*)(cT + ob) = make_float4(c4[0], c4[1], c4[2], c4[3]);
        }
        if (t + 1 < TSTEPS) {   // prefetch next step's input projection
            const float* gb = gatesT + (size_t)(t + 1) * NG * BATCH + m;
#pragma unroll
            for (int q = 0; q < 4; q++)
#pragma unroll
                for (int g = 0; g < 4; g++)
                    gt[q * 4 + g] = gb[(size_t)(g * HID + j0 + nhalf * 4 + q) * BATCH];
        }
        // loop top: acquire-wait for generation t+1
    }
}

// =================================================================================
extern "C" void kernel_launch(void* const* d_in, const int* in_sizes, int n_in,
                              void* d_out, int out_size)
{
    const float* x   = (const float*)d_in[0];
    const float* wih = (const float*)d_in[1];
    const float* whh = (const float*)d_in[2];
    const float* bih = (const float*)d_in[3];
    const float* bhh = (const float*)d_in[4];
    float* out = (float*)d_out;

    cudaFuncSetAttribute(lstm_recur, cudaFuncAttributeMaxDynamicSharedMemorySize, SM_TOTAL);

    float  *gatesT;
    __half *hseq16;
    cudaGetSymbolAddress((void**)&gatesT, g_gatesT);
    cudaGetSymbolAddress((void**)&hseq16, g_hseq16);

    float* hT_base = out + (size_t)TSTEPS * BATCH * HID;
    float* cT_base = hT_base + (size_t)NLAYER * BATCH * HID;

    for (int l = 0; l < NLAYER; ++l) {
        const float* Wih = wih + (size_t)l * 1024 * NG;
        const float* Whh = whh + (size_t)l * HID * NG;
        const float* B1  = bih + (size_t)l * NG;
        const float* B2  = bhh + (size_t)l * NG;
        float* hT = hT_base + (size_t)l * BATCH * HID;
        float* cT = cT_base + (size_t)l * BATCH * HID;

        if (l == 0)
            gemm_input<false><<<dim3(NG / 128, TSTEPS), 256>>>(x, Wih, gatesT);
        else
            gemm_input<true ><<<dim3(NG / 128, TSTEPS), 256>>>(hseq16, Wih, gatesT);

        lstm_init<<<256, 256>>>();

        lstm_recur<<<NCTA_R, THR_R, SM_TOTAL>>>(
            Whh, gatesT, B1, B2,
            (l == 0) ? hseq16 : (__half*)nullptr,
            (l == 1) ? out    : (float*)nullptr,
            hT, cT);
    }
}